// round 4
// baseline (speedup 1.0000x reference)
#include <cuda_runtime.h>
#include <cstdint>

#define D 256
#define RT 8      // relations per block in k_rel
#define KT 16     // k-tile width per k-group
#define PADW 20   // smem row stride (floats) for W tiles

typedef unsigned long long u64;

// Scratch (no cudaMalloc allowed).
__device__ float g_sub[D];
__device__ float g_r0[D];
__device__ float g_gi[3 * D];
__device__ float g_obj[2048 * D];   // supports up to R=2048 relations (problem has R=1000)

__device__ __forceinline__ float sigmoidf_(float x) { return 1.0f / (1.0f + expf(-x)); }

__device__ __forceinline__ float wredsum(float v) {
#pragma unroll
    for (int o = 16; o; o >>= 1) v += __shfl_xor_sync(0xffffffffu, v, o);
    return v;
}

// packed f32x2 fma: acc = a*b + acc (2 packed floats)
__device__ __forceinline__ void fma2(u64& acc, u64 a, u64 b) {
    asm("fma.rn.f32x2 %0, %1, %2, %3;" : "=l"(acc) : "l"(a), "l"(b), "l"(acc));
}
__device__ __forceinline__ float unpack_sum(u64 acc) {
    float lo = __uint_as_float((unsigned)(acc & 0xffffffffu));
    float hi = __uint_as_float((unsigned)(acc >> 32));
    return lo + hi;
}

// Coalesced warp dot: row-major W row (256 floats) with vector x.
__device__ __forceinline__ float warp_dot256(const float* __restrict__ Wrow,
                                             const float* __restrict__ x, int lane) {
    const float4* w4 = reinterpret_cast<const float4*>(Wrow);
    const float4* x4 = reinterpret_cast<const float4*>(x);
    float4 a0 = w4[lane],      b0 = x4[lane];
    float4 a1 = w4[lane + 32], b1 = x4[lane + 32];
    float s = a0.x * b0.x + a0.y * b0.y + a0.z * b0.z + a0.w * b0.w
            + a1.x * b1.x + a1.y * b1.y + a1.z * b1.z + a1.w * b1.w;
    return wredsum(s);
}

// ---------------------------------------------------------------------------
// Prolog A: sub = tanh(sub_W @ mask + sub_b).  warp-per-output.
// ---------------------------------------------------------------------------
__global__ void kA_sub(const float* __restrict__ mask, const float* __restrict__ sub_W,
                       const float* __restrict__ sub_b) {
    int lane = threadIdx.x & 31;
    int j = blockIdx.x * 8 + (threadIdx.x >> 5);
    float s = warp_dot256(sub_W + (size_t)j * D, mask, lane);
    if (lane == 0) g_sub[j] = tanhf(s + sub_b[j]);
}

// ---------------------------------------------------------------------------
// Prolog B: r0 = GRUCell(x=enc, h=sub).  warp-per-output.
// ---------------------------------------------------------------------------
__global__ void kB_r0(const float* __restrict__ enc, const float* __restrict__ W_ih,
                      const float* __restrict__ W_hh, const float* __restrict__ b_ih,
                      const float* __restrict__ b_hh) {
    int lane = threadIdx.x & 31;
    int j = blockIdx.x * 8 + (threadIdx.x >> 5);
    float gi[3], gh[3];
#pragma unroll
    for (int g = 0; g < 3; g++) {
        int row = g * D + j;
        gi[g] = warp_dot256(W_ih + (size_t)row * D, enc, lane);
        gh[g] = warp_dot256(W_hh + (size_t)row * D, g_sub, lane);
    }
    if (lane == 0) {
        float rg = sigmoidf_(gi[0] + b_ih[j] + gh[0] + b_hh[j]);
        float zg = sigmoidf_(gi[1] + b_ih[D + j] + gh[1] + b_hh[D + j]);
        float ng = tanhf(gi[2] + b_ih[2 * D + j] + rg * (gh[2] + b_hh[2 * D + j]));
        g_r0[j] = (1.0f - zg) * ng + zg * g_sub[j];
    }
}

// ---------------------------------------------------------------------------
// Prolog C: g_gi = W_ih @ r0 + b_ih  (768 outputs, shared by all edges).
// ---------------------------------------------------------------------------
__global__ void kC_gi(const float* __restrict__ W_ih, const float* __restrict__ b_ih) {
    int lane = threadIdx.x & 31;
    int j = blockIdx.x * 8 + (threadIdx.x >> 5);   // 0..767
    float s = warp_dot256(W_ih + (size_t)j * D, g_r0, lane);
    if (lane == 0) g_gi[j] = s + b_ih[j];
}

// ---------------------------------------------------------------------------
// k_rel v4: 512 threads, split-K. Threads t<256 (group 0) handle k=[0,128),
// t>=256 (group 1) handle k=[128,256); each group has its own KT=16 tile
// buffer (PADW=20 stride -> conflict-free LDS.128 / STS.128). Partial sums
// from group 1 reduced through smem; group 0 does GRU combine / tanh+store.
// ---------------------------------------------------------------------------
__global__ void __launch_bounds__(512, 1)
k_rel(const float* __restrict__ rel_table, const float* __restrict__ W_hh,
      const float* __restrict__ b_hh, const float* __restrict__ obj_W,
      const float* __restrict__ obj_b, int R) {
    extern __shared__ float sm[];
    float* sWbase = sm;                       // 2 * 768 * PADW
    float* s_h    = sm + 2 * 768 * PADW;      // RT * D
    float* s_rj   = s_h + RT * D;             // RT * D
    float* s_red  = s_rj + RT * D;            // 256 * 24

    int t  = threadIdx.x;
    int tt = t & 255;
    int kh = t >> 8;                          // k-group 0/1
    float* sW = sWbase + kh * (768 * PADW);
    int kofs = kh * 128;
    int rbase = blockIdx.x * RT;

    for (int idx = t; idx < RT * D; idx += 512) {
        int r = idx >> 8;
        s_h[idx] = (rbase + r < R) ? rel_table[(size_t)(rbase + r) * D + (idx & 255)] : 0.0f;
    }

    u64 accR[RT], accZ[RT], accN[RT];
#pragma unroll
    for (int r = 0; r < RT; r++) { accR[r] = 0; accZ[r] = 0; accN[r] = 0; }

    // ---- gate phase: this group's k-half, 8 tiles of KT=16 ----
    for (int tile = 0; tile < 128 / KT; tile++) {
        int kbase = kofs + tile * KT;
        __syncthreads();
        // stage 768 rows x 16 cols of W_hh into this group's buffer (coalesced)
#pragma unroll
        for (int i = 0; i < 12; i++) {          // 768*16/4 float4 / 256 threads
            int lin = (i * 256 + tt) * 4;
            int row = lin >> 4;
            int k   = lin & 15;
            float4 v = *reinterpret_cast<const float4*>(&W_hh[(size_t)row * D + kbase + k]);
            *reinterpret_cast<float4*>(&sW[row * PADW + k]) = v;
        }
        __syncthreads();
#pragma unroll
        for (int kk = 0; kk < KT; kk += 4) {
            int kg = kbase + kk;
            ulonglong2 wr = *reinterpret_cast<const ulonglong2*>(&sW[(0 * D + tt) * PADW + kk]);
            ulonglong2 wz = *reinterpret_cast<const ulonglong2*>(&sW[(1 * D + tt) * PADW + kk]);
            ulonglong2 wn = *reinterpret_cast<const ulonglong2*>(&sW[(2 * D + tt) * PADW + kk]);
#pragma unroll
            for (int r = 0; r < RT; r++) {
                ulonglong2 h2 = *reinterpret_cast<const ulonglong2*>(&s_h[r * D + kg]);
                fma2(accR[r], wr.x, h2.x); fma2(accR[r], wr.y, h2.y);
                fma2(accZ[r], wz.x, h2.x); fma2(accZ[r], wz.y, h2.y);
                fma2(accN[r], wn.x, h2.x); fma2(accN[r], wn.y, h2.y);
            }
        }
    }
    __syncthreads();
    if (kh == 1) {
#pragma unroll
        for (int r = 0; r < RT; r++) {
            s_red[tt * 24 + r]      = unpack_sum(accR[r]);
            s_red[tt * 24 + 8 + r]  = unpack_sum(accZ[r]);
            s_red[tt * 24 + 16 + r] = unpack_sum(accN[r]);
        }
    }
    __syncthreads();
    if (kh == 0) {
        float ir = g_gi[tt], iz = g_gi[D + tt], in_ = g_gi[2 * D + tt];
        float bhr = b_hh[tt], bhz = b_hh[D + tt], bhn = b_hh[2 * D + tt];
#pragma unroll
        for (int r = 0; r < RT; r++) {
            float aR = unpack_sum(accR[r]) + s_red[tt * 24 + r];
            float aZ = unpack_sum(accZ[r]) + s_red[tt * 24 + 8 + r];
            float aN = unpack_sum(accN[r]) + s_red[tt * 24 + 16 + r];
            float rg = sigmoidf_(ir + aR + bhr);
            float zg = sigmoidf_(iz + aZ + bhz);
            float ng = tanhf(in_ + rg * (aN + bhn));
            s_rj[r * D + tt] = (1.0f - zg) * ng + zg * s_h[r * D + tt];
        }
    }

    // ---- obj phase: tanh(obj_W @ rj + obj_b), same split-K ----
    u64 accO[RT];
#pragma unroll
    for (int r = 0; r < RT; r++) accO[r] = 0;

    for (int tile = 0; tile < 128 / KT; tile++) {
        int kbase = kofs + tile * KT;
        __syncthreads();   // also orders s_rj writes before reads below (tile 0)
#pragma unroll
        for (int i = 0; i < 4; i++) {           // 256*16/4 float4 / 256 threads
            int lin = (i * 256 + tt) * 4;
            int row = lin >> 4;
            int k   = lin & 15;
            float4 v = *reinterpret_cast<const float4*>(&obj_W[(size_t)row * D + kbase + k]);
            *reinterpret_cast<float4*>(&sW[row * PADW + k]) = v;
        }
        __syncthreads();
#pragma unroll
        for (int kk = 0; kk < KT; kk += 4) {
            int kg = kbase + kk;
            ulonglong2 wo = *reinterpret_cast<const ulonglong2*>(&sW[tt * PADW + kk]);
#pragma unroll
            for (int r = 0; r < RT; r++) {
                ulonglong2 h2 = *reinterpret_cast<const ulonglong2*>(&s_rj[r * D + kg]);
                fma2(accO[r], wo.x, h2.x); fma2(accO[r], wo.y, h2.y);
            }
        }
    }
    __syncthreads();
    if (kh == 1) {
#pragma unroll
        for (int r = 0; r < RT; r++) s_red[tt * 24 + r] = unpack_sum(accO[r]);
    }
    __syncthreads();
    if (kh == 0) {
        float ob = obj_b[tt];
#pragma unroll
        for (int r = 0; r < RT; r++) {
            if (rbase + r < R)
                g_obj[(size_t)(rbase + r) * D + tt] =
                    tanhf(unpack_sum(accO[r]) + s_red[tt * 24 + r] + ob);
        }
    }
}

#define REL_SMEM ((2 * 768 * PADW + 2 * RT * D + 256 * 24) * 4)

// ---------------------------------------------------------------------------
// Seed row (seed never collides with tail_ids in this problem; tails win
// anyway per reference order when scatters run after/concurrently).
// ---------------------------------------------------------------------------
__global__ void k_seed(const int* __restrict__ seed_p, float* __restrict__ out) {
    int t = threadIdx.x;
    int seed = *seed_p;
    out[(size_t)seed * D + t] = g_sub[t];
}

// ---------------------------------------------------------------------------
// Scatter pass 1 (independent of all compute): entity rows (state==1).
// Warp handles 4 rows, lane copies 2 float4/row; loads batched before stores.
// ---------------------------------------------------------------------------
__global__ void k_scat_ent(const float* __restrict__ ent_table, const int* __restrict__ tail_ids,
                           const int* __restrict__ tails_state, const int* __restrict__ origin_ids,
                           float* __restrict__ out, int E) {
    int warp = threadIdx.x >> 5;
    int lane = threadIdx.x & 31;
    int base = (blockIdx.x * 8 + warp) * 4;

    float4 v[4][2];
    float4* dst[4];
    bool ok[4];
#pragma unroll
    for (int i = 0; i < 4; i++) {
        int row = base + i;
        ok[i] = (row < E) && (tails_state[row] == 1);
        if (ok[i]) {
            const float4* src = reinterpret_cast<const float4*>(ent_table)
                                + (size_t)origin_ids[row] * (D / 4);
            dst[i] = reinterpret_cast<float4*>(out) + (size_t)tail_ids[row] * (D / 4);
            v[i][0] = src[lane];
            v[i][1] = src[lane + 32];
        }
    }
#pragma unroll
    for (int i = 0; i < 4; i++) {
        if (ok[i]) {
            dst[i][lane] = v[i][0];
            dst[i][lane + 32] = v[i][1];
        }
    }
}

// ---------------------------------------------------------------------------
// Scatter pass 2 (after k_rel): obj rows (state!=1). Source is L2-resident.
// ---------------------------------------------------------------------------
__global__ void k_scat_obj(const int* __restrict__ rel_ids, const int* __restrict__ tail_ids,
                           const int* __restrict__ tails_state, float* __restrict__ out, int E) {
    int warp = threadIdx.x >> 5;
    int lane = threadIdx.x & 31;
    int base = (blockIdx.x * 8 + warp) * 4;

    float4 v[4][2];
    float4* dst[4];
    bool ok[4];
#pragma unroll
    for (int i = 0; i < 4; i++) {
        int row = base + i;
        ok[i] = (row < E) && (tails_state[row] != 1);
        if (ok[i]) {
            const float4* src = reinterpret_cast<const float4*>(g_obj)
                                + (size_t)rel_ids[row] * (D / 4);
            dst[i] = reinterpret_cast<float4*>(out) + (size_t)tail_ids[row] * (D / 4);
            v[i][0] = src[lane];
            v[i][1] = src[lane + 32];
        }
    }
#pragma unroll
    for (int i = 0; i < 4; i++) {
        if (ok[i]) {
            dst[i][lane] = v[i][0];
            dst[i][lane + 32] = v[i][1];
        }
    }
}

// ---------------------------------------------------------------------------
extern "C" void kernel_launch(void* const* d_in, const int* in_sizes, int n_in,
                              void* d_out, int out_size) {
    const float* enc       = (const float*)d_in[0];
    const float* mask      = (const float*)d_in[1];
    const float* ent_table = (const float*)d_in[2];
    const float* rel_table = (const float*)d_in[3];
    const float* W_ih      = (const float*)d_in[4];
    const float* W_hh      = (const float*)d_in[5];
    const float* b_ih      = (const float*)d_in[6];
    const float* b_hh      = (const float*)d_in[7];
    const float* sub_W     = (const float*)d_in[8];
    const float* sub_b     = (const float*)d_in[9];
    const float* obj_W     = (const float*)d_in[10];
    const float* obj_b     = (const float*)d_in[11];
    const int*   rel_ids   = (const int*)d_in[12];
    const int*   tail_ids  = (const int*)d_in[13];
    const int*   tails_st  = (const int*)d_in[14];
    const int*   origin    = (const int*)d_in[15];
    const int*   seed_p    = (const int*)d_in[16];
    float* out = (float*)d_out;

    int E = in_sizes[12];
    int R = in_sizes[3] / D;

    // One-time host-side setup (first call is the uncaptured correctness run).
    static cudaStream_t s1 = nullptr;
    static cudaEvent_t ev0 = nullptr, ev1 = nullptr;
    if (s1 == nullptr) {
        cudaStreamCreateWithFlags(&s1, cudaStreamNonBlocking);
        cudaEventCreateWithFlags(&ev0, cudaEventDisableTiming);
        cudaEventCreateWithFlags(&ev1, cudaEventDisableTiming);
        cudaFuncSetAttribute(k_rel, cudaFuncAttributeMaxDynamicSharedMemorySize, REL_SMEM);
    }

    // Fork: compute chain on s1, entity scatter concurrently on the main stream.
    cudaEventRecord(ev0, 0);
    cudaStreamWaitEvent(s1, ev0, 0);

    kA_sub<<<32, 256, 0, s1>>>(mask, sub_W, sub_b);
    kB_r0<<<32, 256, 0, s1>>>(enc, W_ih, W_hh, b_ih, b_hh);
    kC_gi<<<96, 256, 0, s1>>>(W_ih, b_ih);
    k_seed<<<1, D, 0, s1>>>(seed_p, out);
    k_rel<<<(R + RT - 1) / RT, 512, REL_SMEM, s1>>>(rel_table, W_hh, b_hh, obj_W, obj_b, R);
    cudaEventRecord(ev1, s1);

    k_scat_ent<<<(E + 31) / 32, 256>>>(ent_table, tail_ids, tails_st, origin, out, E);

    // Join: obj scatter needs g_obj from k_rel.
    cudaStreamWaitEvent(0, ev1, 0);
    k_scat_obj<<<(E + 31) / 32, 256>>>(rel_ids, tail_ids, tails_st, out, E);
}

// round 5
// speedup vs baseline: 1.1509x; 1.1509x over previous
#include <cuda_runtime.h>
#include <cstdint>

#define D 256
#define RT 8      // relations per block in k_rel
#define KT 32     // k-tile width staged in smem
#define PADW 36   // smem row stride (floats): odd quad-stride -> conflict-free LDS.128

typedef unsigned long long u64;

// Scratch (no cudaMalloc allowed).
__device__ float g_sub[D];
__device__ float g_r0[D];
__device__ float g_gi[3 * D];
__device__ float g_obj[2048 * D];   // supports up to R=2048 relations (problem has R=1000)

__device__ __forceinline__ float sigmoidf_(float x) { return 1.0f / (1.0f + expf(-x)); }

__device__ __forceinline__ float wredsum(float v) {
#pragma unroll
    for (int o = 16; o; o >>= 1) v += __shfl_xor_sync(0xffffffffu, v, o);
    return v;
}

// packed f32x2 fma: acc = a*b + acc (2 packed floats)
__device__ __forceinline__ void fma2(u64& acc, u64 a, u64 b) {
    asm("fma.rn.f32x2 %0, %1, %2, %3;" : "=l"(acc) : "l"(a), "l"(b), "l"(acc));
}
__device__ __forceinline__ float unpack_sum(u64 acc) {
    float lo = __uint_as_float((unsigned)(acc & 0xffffffffu));
    float hi = __uint_as_float((unsigned)(acc >> 32));
    return lo + hi;
}

// Coalesced warp dot: row-major W row (256 floats) with vector x.
__device__ __forceinline__ float warp_dot256(const float* __restrict__ Wrow,
                                             const float* __restrict__ x, int lane) {
    const float4* w4 = reinterpret_cast<const float4*>(Wrow);
    const float4* x4 = reinterpret_cast<const float4*>(x);
    float4 a0 = w4[lane],      b0 = x4[lane];
    float4 a1 = w4[lane + 32], b1 = x4[lane + 32];
    float s = a0.x * b0.x + a0.y * b0.y + a0.z * b0.z + a0.w * b0.w
            + a1.x * b1.x + a1.y * b1.y + a1.z * b1.z + a1.w * b1.w;
    return wredsum(s);
}

// ---------------------------------------------------------------------------
// Prolog A: sub = tanh(sub_W @ mask + sub_b).  warp-per-output.
// ---------------------------------------------------------------------------
__global__ void kA_sub(const float* __restrict__ mask, const float* __restrict__ sub_W,
                       const float* __restrict__ sub_b) {
    int lane = threadIdx.x & 31;
    int j = blockIdx.x * 8 + (threadIdx.x >> 5);
    float s = warp_dot256(sub_W + (size_t)j * D, mask, lane);
    if (lane == 0) g_sub[j] = tanhf(s + sub_b[j]);
}

// ---------------------------------------------------------------------------
// Prolog B: r0 = GRUCell(x=enc, h=sub).  warp-per-output.
// ---------------------------------------------------------------------------
__global__ void kB_r0(const float* __restrict__ enc, const float* __restrict__ W_ih,
                      const float* __restrict__ W_hh, const float* __restrict__ b_ih,
                      const float* __restrict__ b_hh) {
    int lane = threadIdx.x & 31;
    int j = blockIdx.x * 8 + (threadIdx.x >> 5);
    float gi[3], gh[3];
#pragma unroll
    for (int g = 0; g < 3; g++) {
        int row = g * D + j;
        gi[g] = warp_dot256(W_ih + (size_t)row * D, enc, lane);
        gh[g] = warp_dot256(W_hh + (size_t)row * D, g_sub, lane);
    }
    if (lane == 0) {
        float rg = sigmoidf_(gi[0] + b_ih[j] + gh[0] + b_hh[j]);
        float zg = sigmoidf_(gi[1] + b_ih[D + j] + gh[1] + b_hh[D + j]);
        float ng = tanhf(gi[2] + b_ih[2 * D + j] + rg * (gh[2] + b_hh[2 * D + j]));
        g_r0[j] = (1.0f - zg) * ng + zg * g_sub[j];
    }
}

// ---------------------------------------------------------------------------
// Prolog C: g_gi = W_ih @ r0 + b_ih  (768 outputs, shared by all edges).
// ---------------------------------------------------------------------------
__global__ void kC_gi(const float* __restrict__ W_ih, const float* __restrict__ b_ih) {
    int lane = threadIdx.x & 31;
    int j = blockIdx.x * 8 + (threadIdx.x >> 5);   // 0..767
    float s = warp_dot256(W_ih + (size_t)j * D, g_r0, lane);
    if (lane == 0) g_gi[j] = s + b_ih[j];
}

// ---------------------------------------------------------------------------
// k_rel v5: 768 threads (24 warps/SM). Gate phase: thread t owns W_hh row t
// (gate t/256, dim t&255), 8 relation accumulators in packed f32x2; W staged
// through smem (coalesced LDG, conflict-free PADW=36). Partial gate sums
// exchanged through smem (overlaid on sW); threads<256 do the GRU combine.
// Obj phase: 2-way split-K on threads<512, smem reduce, tanh+store.
// ---------------------------------------------------------------------------
__global__ void __launch_bounds__(768, 1)
k_rel(const float* __restrict__ rel_table, const float* __restrict__ W_hh,
      const float* __restrict__ b_hh, const float* __restrict__ obj_W,
      const float* __restrict__ obj_b, int R) {
    extern __shared__ float sm[];
    float* sW   = sm;                       // 768 * PADW floats (27648)
    float* s_h  = sm + 768 * PADW;          // RT * D
    float* s_rj = s_h + RT * D;             // RT * D
    // overlays inside sW (live only between phases):
    float* s_part = sW;                     // 768*8 gate partials (freed before obj staging)
    float* s_red  = sW + 16384;             // 256*8 obj partials (beyond obj staging's 9216)

    int t = threadIdx.x;
    int rbase = blockIdx.x * RT;

    for (int idx = t; idx < RT * D; idx += 768) {
        int r = idx >> 8;
        s_h[idx] = (rbase + r < R) ? rel_table[(size_t)(rbase + r) * D + (idx & 255)] : 0.0f;
    }

    // ---- gate phase: acc[r] = dot(W_hh[t], h[r]) ----
    u64 acc[RT];
#pragma unroll
    for (int r = 0; r < RT; r++) acc[r] = 0;

    for (int tile = 0; tile < D / KT; tile++) {
        __syncthreads();
        // stage 768 rows x 32 cols of W_hh (6144 float4 over 768 threads)
#pragma unroll
        for (int i = 0; i < 8; i++) {
            int lin = (i * 768 + t) * 4;
            int row = lin >> 5;
            int k   = lin & 31;
            float4 v = *reinterpret_cast<const float4*>(&W_hh[(size_t)row * D + tile * KT + k]);
            *reinterpret_cast<float4*>(&sW[row * PADW + k]) = v;
        }
        __syncthreads();
#pragma unroll
        for (int kk = 0; kk < KT; kk += 4) {
            int kg = tile * KT + kk;
            ulonglong2 w = *reinterpret_cast<const ulonglong2*>(&sW[t * PADW + kk]);
#pragma unroll
            for (int r = 0; r < RT; r++) {
                ulonglong2 h2 = *reinterpret_cast<const ulonglong2*>(&s_h[r * D + kg]);
                fma2(acc[r], w.x, h2.x);
                fma2(acc[r], w.y, h2.y);
            }
        }
    }
    __syncthreads();
#pragma unroll
    for (int r = 0; r < RT; r++) s_part[t * 8 + r] = unpack_sum(acc[r]);
    __syncthreads();

    // ---- GRU combine (threads < 256) -> s_rj ----
    if (t < D) {
        float ir = g_gi[t], iz = g_gi[D + t], in_ = g_gi[2 * D + t];
        float bhr = b_hh[t], bhz = b_hh[D + t], bhn = b_hh[2 * D + t];
#pragma unroll
        for (int r = 0; r < RT; r++) {
            float aR = s_part[t * 8 + r];
            float aZ = s_part[(D + t) * 8 + r];
            float aN = s_part[(2 * D + t) * 8 + r];
            float rg = sigmoidf_(ir + aR + bhr);
            float zg = sigmoidf_(iz + aZ + bhz);
            float ng = tanhf(in_ + rg * (aN + bhn));
            s_rj[r * D + t] = (1.0f - zg) * ng + zg * s_h[r * D + t];
        }
    }

    // ---- obj phase: tanh(obj_W @ rj + obj_b), 2-way split-K on threads<512 ----
    u64 accO[RT];
#pragma unroll
    for (int r = 0; r < RT; r++) accO[r] = 0;
    int kh = t >> 8;        // 0 / 1 / 2
    int tt = t & 255;

    for (int tile = 0; tile < D / KT; tile++) {
        __syncthreads();    // first iter also orders s_rj writes & frees s_part
        // stage 256 rows x 32 cols of obj_W (2048 float4 over 768 threads)
#pragma unroll
        for (int i = 0; i < 3; i++) {
            int f4 = i * 768 + t;
            if (f4 < 2048) {
                int lin = f4 * 4;
                int row = lin >> 5;
                int k   = lin & 31;
                *reinterpret_cast<float4*>(&sW[row * PADW + k]) =
                    *reinterpret_cast<const float4*>(&obj_W[(size_t)row * D + tile * KT + k]);
            }
        }
        __syncthreads();
        if (kh == (tile >> 2)) {   // kh=0: tiles 0-3 (k<128), kh=1: tiles 4-7
#pragma unroll
            for (int kk = 0; kk < KT; kk += 4) {
                int kg = tile * KT + kk;
                ulonglong2 w = *reinterpret_cast<const ulonglong2*>(&sW[tt * PADW + kk]);
#pragma unroll
                for (int r = 0; r < RT; r++) {
                    ulonglong2 h2 = *reinterpret_cast<const ulonglong2*>(&s_rj[r * D + kg]);
                    fma2(accO[r], w.x, h2.x);
                    fma2(accO[r], w.y, h2.y);
                }
            }
        }
    }
    __syncthreads();
    if (kh == 1) {
#pragma unroll
        for (int r = 0; r < RT; r++) s_red[tt * 8 + r] = unpack_sum(accO[r]);
    }
    __syncthreads();
    if (kh == 0) {
        float ob = obj_b[tt];
#pragma unroll
        for (int r = 0; r < RT; r++) {
            if (rbase + r < R)
                g_obj[(size_t)(rbase + r) * D + tt] =
                    tanhf(unpack_sum(accO[r]) + s_red[tt * 8 + r] + ob);
        }
    }
}

#define REL_SMEM ((768 * PADW + 2 * RT * D) * 4)

// ---------------------------------------------------------------------------
// Single-pass scatter (+ seed row folded into block 0; seed==E never collides
// with tail_ids==0..E-1 in this problem). Streaming stores (__stcs) keep the
// 205MB of output writes from evicting entity-gather lines in L2.
// ---------------------------------------------------------------------------
__global__ void k_scatter(const float* __restrict__ ent_table, const int* __restrict__ rel_ids,
                          const int* __restrict__ tail_ids, const int* __restrict__ tails_state,
                          const int* __restrict__ origin_ids, const int* __restrict__ seed_p,
                          float* __restrict__ out, int E) {
    if (blockIdx.x == 0) {
        int seed = *seed_p;
        out[(size_t)seed * D + threadIdx.x] = g_sub[threadIdx.x];
    }

    int warp = threadIdx.x >> 5;
    int lane = threadIdx.x & 31;
    int base = (blockIdx.x * 8 + warp) * 4;

    float4 v[4][2];
    float4* dst[4];
    bool ok[4];
#pragma unroll
    for (int i = 0; i < 4; i++) {
        int row = base + i;
        ok[i] = row < E;
        if (ok[i]) {
            int st = tails_state[row];
            const float4* src = (st == 1)
                ? reinterpret_cast<const float4*>(ent_table) + (size_t)origin_ids[row] * (D / 4)
                : reinterpret_cast<const float4*>(g_obj) + (size_t)rel_ids[row] * (D / 4);
            dst[i] = reinterpret_cast<float4*>(out) + (size_t)tail_ids[row] * (D / 4);
            v[i][0] = src[lane];
            v[i][1] = src[lane + 32];
        }
    }
#pragma unroll
    for (int i = 0; i < 4; i++) {
        if (ok[i]) {
            __stcs(&dst[i][lane], v[i][0]);
            __stcs(&dst[i][lane + 32], v[i][1]);
        }
    }
}

// ---------------------------------------------------------------------------
extern "C" void kernel_launch(void* const* d_in, const int* in_sizes, int n_in,
                              void* d_out, int out_size) {
    const float* enc       = (const float*)d_in[0];
    const float* mask      = (const float*)d_in[1];
    const float* ent_table = (const float*)d_in[2];
    const float* rel_table = (const float*)d_in[3];
    const float* W_ih      = (const float*)d_in[4];
    const float* W_hh      = (const float*)d_in[5];
    const float* b_ih      = (const float*)d_in[6];
    const float* b_hh      = (const float*)d_in[7];
    const float* sub_W     = (const float*)d_in[8];
    const float* sub_b     = (const float*)d_in[9];
    const float* obj_W     = (const float*)d_in[10];
    const float* obj_b     = (const float*)d_in[11];
    const int*   rel_ids   = (const int*)d_in[12];
    const int*   tail_ids  = (const int*)d_in[13];
    const int*   tails_st  = (const int*)d_in[14];
    const int*   origin    = (const int*)d_in[15];
    const int*   seed_p    = (const int*)d_in[16];
    float* out = (float*)d_out;

    int E = in_sizes[12];
    int R = in_sizes[3] / D;

    static bool init = false;
    if (!init) {
        cudaFuncSetAttribute(k_rel, cudaFuncAttributeMaxDynamicSharedMemorySize, REL_SMEM);
        init = true;
    }

    kA_sub<<<32, 256>>>(mask, sub_W, sub_b);
    kB_r0<<<32, 256>>>(enc, W_ih, W_hh, b_ih, b_hh);
    kC_gi<<<96, 256>>>(W_ih, b_ih);
    k_rel<<<(R + RT - 1) / RT, 768, REL_SMEM>>>(rel_table, W_hh, b_hh, obj_W, obj_b, R);
    k_scatter<<<(E + 31) / 32, 256>>>(ent_table, rel_ids, tail_ids, tails_st, origin,
                                      seed_p, out, E);
}